// round 2
// baseline (speedup 1.0000x reference)
#include <cuda_runtime.h>
#include <cuda_bf16.h>
#include <math.h>

typedef unsigned long long ull_t;

// ---------------- problem dims ----------------
#define BB     16
#define CQ     256
#define CK     2048
#define NN     4096      // 64*64
#define NCLS   40
#define HID    1024
#define FDIM   2304      // CQ + CK

// ---------------- device scratch (statics are the sanctioned scratch path) ----------------
__device__ float g_Wqt[CQ * CQ];                 // [ci][co]
__device__ float g_Wkt[CK * CQ];                 // [ci][co]
__device__ float g_Q[(size_t)BB * CQ * NN];      // [b][c][m]
__device__ float g_K[(size_t)BB * CQ * NN];      // [b][c][n]
__device__ float g_S[(size_t)BB * NN * NN];      // [b][m][n]  (1.07 GB)
__device__ float g_rowmax[BB * NN];
__device__ float g_colsum[BB * NN];              // = w[b][n] (already /N)
__device__ float g_simg[BB * CQ];
__device__ float g_mimg[BB * CQ];
__device__ float g_spc[BB * CK];
__device__ float g_fused[BB * FDIM];
__device__ float g_h[BB * HID];

// ---------------- packed f32x2 helpers ----------------
__device__ __forceinline__ ull_t pack2(float x, float y) {
    ull_t r;
    asm("mov.b64 %0, {%1, %2};" : "=l"(r) : "f"(x), "f"(y));
    return r;
}
__device__ __forceinline__ void unpack2(ull_t v, float &x, float &y) {
    asm("mov.b64 {%0, %1}, %2;" : "=f"(x), "=f"(y) : "l"(v));
}
__device__ __forceinline__ void ffma2(ull_t &acc, ull_t a, ull_t b) {
    asm("fma.rn.f32x2 %0, %1, %2, %0;" : "+l"(acc) : "l"(a), "l"(b));
}

// fast exp for x <= 0 (FFMA-only, no MUFU). Accurate to ~1e-7 rel.
__device__ __forceinline__ float fexp(float x) {
    float t = x * 1.4426950408889634f;      // log2(e)
    t = fmaxf(t, -63.0f);
    float z = t + 12582912.0f;              // round-to-nearest-int magic (2^23+2^22)
    int   n = __float_as_int(z) - 0x4B400000;
    float r = t - (z - 12582912.0f);        // r in [-0.5, 0.5]
    float u = r * 0.6931471805599453f;      // ln2
    float p = 1.38888889e-3f;
    p = fmaf(p, u, 8.33333333e-3f);
    p = fmaf(p, u, 4.16666667e-2f);
    p = fmaf(p, u, 1.66666667e-1f);
    p = fmaf(p, u, 0.5f);
    p = fmaf(p, u, 1.0f);
    p = fmaf(p, u, 1.0f);
    return p * __int_as_float((n + 127) << 23);
}

// ---------------- shared 128x128x16 fp32(x2) micro-GEMM tile ----------------
__device__ __forceinline__ void mma_tile(const float (&As)[16][128], const float (&Bs)[16][128],
                                         ull_t (&acc)[8][4], int tx, int ty) {
#pragma unroll
    for (int k = 0; k < 16; k++) {
        const float4 a0 = *(const float4 *)&As[k][ty * 8];
        const float4 a1 = *(const float4 *)&As[k][ty * 8 + 4];
        const ull_t  b0 = *(const ull_t *)&Bs[k][tx * 8];
        const ull_t  b1 = *(const ull_t *)&Bs[k][tx * 8 + 2];
        const ull_t  b2 = *(const ull_t *)&Bs[k][tx * 8 + 4];
        const ull_t  b3 = *(const ull_t *)&Bs[k][tx * 8 + 6];
        ull_t aa;
#define ROW_FMA(i, ax)                                                      \
        aa = pack2(ax, ax);                                                 \
        ffma2(acc[i][0], aa, b0); ffma2(acc[i][1], aa, b1);                 \
        ffma2(acc[i][2], aa, b2); ffma2(acc[i][3], aa, b3);
        ROW_FMA(0, a0.x) ROW_FMA(1, a0.y) ROW_FMA(2, a0.z) ROW_FMA(3, a0.w)
        ROW_FMA(4, a1.x) ROW_FMA(5, a1.y) ROW_FMA(6, a1.z) ROW_FMA(7, a1.w)
#undef ROW_FMA
    }
}

// ---------------- weight transpose ----------------
__global__ void transpose_kernel(const float *__restrict__ in, float *__restrict__ out, int R, int C) {
    __shared__ float t[32][33];
    int c0 = blockIdx.x * 32, r0 = blockIdx.y * 32;
    int x = threadIdx.x, y = threadIdx.y;
#pragma unroll
    for (int i = y; i < 32; i += 8)
        t[i][x] = in[(size_t)(r0 + i) * C + c0 + x];
    __syncthreads();
#pragma unroll
    for (int i = y; i < 32; i += 8)
        out[(size_t)(c0 + i) * R + r0 + x] = t[x][i];
}

// ---------------- conv1x1 projection: Out[b][co][n] = sum_ci Wt[ci][co] * X[b][ci][n] + bias[co] ----------------
__global__ void __launch_bounds__(256) proj_kernel(const float *__restrict__ Wt,
                                                   const float *__restrict__ X,
                                                   const float *__restrict__ bias,
                                                   float *__restrict__ Out, int Kdim) {
    __shared__ float As[16][128];
    __shared__ float Bs[16][128];
    const int b = blockIdx.z;
    const int m0 = blockIdx.y * 128;
    const int n0 = blockIdx.x * 128;
    const int tid = threadIdx.x, tx = tid & 15, ty = tid >> 4;

    ull_t acc[8][4];
#pragma unroll
    for (int i = 0; i < 8; i++)
#pragma unroll
        for (int j = 0; j < 4; j++) acc[i][j] = 0ull;

    const int nkt = Kdim >> 4;
    for (int kt = 0; kt < nkt; kt++) {
        const int k0 = kt * 16;
        __syncthreads();
#pragma unroll
        for (int it = 0; it < 2; it++) {
            int ff = tid + it * 256;
            int k = ff >> 5, c4 = (ff & 31) * 4;
            *(float4 *)&As[k][c4] = *(const float4 *)&Wt[(size_t)(k0 + k) * CQ + m0 + c4];
            *(float4 *)&Bs[k][c4] = *(const float4 *)&X[((size_t)b * Kdim + k0 + k) * NN + n0 + c4];
        }
        __syncthreads();
        mma_tile(As, Bs, acc, tx, ty);
    }

#pragma unroll
    for (int i = 0; i < 8; i++) {
        const int m = m0 + ty * 8 + i;
        const float bv = bias[m];
        float v[8];
        unpack2(acc[i][0], v[0], v[1]); unpack2(acc[i][1], v[2], v[3]);
        unpack2(acc[i][2], v[4], v[5]); unpack2(acc[i][3], v[6], v[7]);
        float4 s0 = make_float4(v[0] + bv, v[1] + bv, v[2] + bv, v[3] + bv);
        float4 s1 = make_float4(v[4] + bv, v[5] + bv, v[6] + bv, v[7] + bv);
        size_t base = ((size_t)b * CQ + m) * NN + n0 + tx * 8;
        *(float4 *)&Out[base]     = s0;
        *(float4 *)&Out[base + 4] = s1;
    }
}

// ---------------- pass1: S = Q^T K, store S, track row max; also zero colsum ----------------
__global__ void __launch_bounds__(256) pass1_kernel() {
    __shared__ float As[16][128];
    __shared__ float Bs[16][128];
    const int b = blockIdx.y;
    const int m0 = blockIdx.x * 128;
    const int tid = threadIdx.x, tx = tid & 15, ty = tid >> 4;

    if (tid < 128) g_colsum[b * NN + m0 + tid] = 0.f;

    float M[8];
#pragma unroll
    for (int i = 0; i < 8; i++) M[i] = -1e30f;

    for (int nc = 0; nc < 32; nc++) {
        const int n0 = nc * 128;
        ull_t acc[8][4];
#pragma unroll
        for (int i = 0; i < 8; i++)
#pragma unroll
            for (int j = 0; j < 4; j++) acc[i][j] = 0ull;

#pragma unroll 1
        for (int kt = 0; kt < 16; kt++) {
            const int k0 = kt * 16;
            __syncthreads();
#pragma unroll
            for (int it = 0; it < 2; it++) {
                int ff = tid + it * 256;
                int k = ff >> 5, c4 = (ff & 31) * 4;
                *(float4 *)&As[k][c4] = *(const float4 *)&g_Q[((size_t)b * CQ + k0 + k) * NN + m0 + c4];
                *(float4 *)&Bs[k][c4] = *(const float4 *)&g_K[((size_t)b * CQ + k0 + k) * NN + n0 + c4];
            }
            __syncthreads();
            mma_tile(As, Bs, acc, tx, ty);
        }

        // epilogue: unpack, running row max (reduced over the 16 tx threads), store S
#pragma unroll
        for (int i = 0; i < 8; i++) {
            float v[8];
            unpack2(acc[i][0], v[0], v[1]); unpack2(acc[i][1], v[2], v[3]);
            unpack2(acc[i][2], v[4], v[5]); unpack2(acc[i][3], v[6], v[7]);
            float vmax = v[0];
#pragma unroll
            for (int j = 1; j < 8; j++) vmax = fmaxf(vmax, v[j]);
#pragma unroll
            for (int off = 1; off < 16; off <<= 1)
                vmax = fmaxf(vmax, __shfl_xor_sync(0xffffffffu, vmax, off));
            M[i] = fmaxf(M[i], vmax);
            size_t base = ((size_t)(b * NN + m0 + ty * 8 + i)) * NN + n0 + tx * 8;
            *(float4 *)&g_S[base]     = make_float4(v[0], v[1], v[2], v[3]);
            *(float4 *)&g_S[base + 4] = make_float4(v[4], v[5], v[6], v[7]);
        }
    }

    if (tx == 0) {
#pragma unroll
        for (int i = 0; i < 8; i++) g_rowmax[b * NN + m0 + ty * 8 + i] = M[i];
    }
}

// ---------------- pass2: stream S, softmax rows, accumulate column weights w = colsum/N ----------------
__global__ void __launch_bounds__(256) pass2_kernel() {
    const int b = blockIdx.y;
    const int m0 = blockIdx.x * 128;
    const int tid = threadIdx.x;

    __shared__ float sM[128];
    __shared__ float sred[8];
    __shared__ float sLinv;

    if (tid < 128) sM[tid] = g_rowmax[b * NN + m0 + tid];
    __syncthreads();

    float acc[4][4];
#pragma unroll
    for (int jj = 0; jj < 4; jj++)
#pragma unroll
        for (int q = 0; q < 4; q++) acc[jj][q] = 0.f;

    const int nbase = tid * 4;
    for (int r = 0; r < 128; r++) {
        const float Mrow = sM[r];
        const float *Srow = &g_S[((size_t)(b * NN + m0 + r)) * NN];
        float u[4][4];
        float psum = 0.f;
#pragma unroll
        for (int jj = 0; jj < 4; jj++) {
            float4 v = *(const float4 *)&Srow[nbase + jj * 1024];
            u[jj][0] = fexp(v.x - Mrow);
            u[jj][1] = fexp(v.y - Mrow);
            u[jj][2] = fexp(v.z - Mrow);
            u[jj][3] = fexp(v.w - Mrow);
            psum += (u[jj][0] + u[jj][1]) + (u[jj][2] + u[jj][3]);
        }
#pragma unroll
        for (int off = 16; off; off >>= 1) psum += __shfl_xor_sync(0xffffffffu, psum, off);
        if ((tid & 31) == 0) sred[tid >> 5] = psum;
        __syncthreads();
        if (tid == 0) {
            float L = 0.f;
#pragma unroll
            for (int i = 0; i < 8; i++) L += sred[i];
            sLinv = 1.0f / L;
        }
        __syncthreads();
        const float linv = sLinv;
#pragma unroll
        for (int jj = 0; jj < 4; jj++)
#pragma unroll
            for (int q = 0; q < 4; q++) acc[jj][q] = fmaf(u[jj][q], linv, acc[jj][q]);
    }

    const float invn = 1.0f / (float)NN;
#pragma unroll
    for (int jj = 0; jj < 4; jj++)
#pragma unroll
        for (int q = 0; q < 4; q++)
            atomicAdd(&g_colsum[b * NN + nbase + jj * 1024 + q], acc[jj][q] * invn);
}

// ---------------- weighted pooling: s_img / mean_img / s_pc ----------------
__global__ void __launch_bounds__(256) pool_kernel(const float *__restrict__ img,
                                                   const float *__restrict__ pc) {
    const int b = blockIdx.y, c = blockIdx.x, tid = threadIdx.x;
    const bool isimg = (c < CQ);
    const float *X = isimg ? img + ((size_t)(b * CQ + c)) * NN
                           : pc + ((size_t)(b * CK + (c - CQ))) * NN;
    const float *w = &g_colsum[b * NN];

    float sw = 0.f, sm = 0.f;
#pragma unroll
    for (int j = 0; j < 4; j++) {
        float4 xv = *(const float4 *)&X[tid * 4 + j * 1024];
        float4 wv = *(const float4 *)&w[tid * 4 + j * 1024];
        sw += xv.x * wv.x + xv.y * wv.y + xv.z * wv.z + xv.w * wv.w;
        sm += (xv.x + xv.y) + (xv.z + xv.w);
    }
#pragma unroll
    for (int off = 16; off; off >>= 1) {
        sw += __shfl_xor_sync(0xffffffffu, sw, off);
        sm += __shfl_xor_sync(0xffffffffu, sm, off);
    }
    __shared__ float r1[8], r2[8];
    if ((tid & 31) == 0) { r1[tid >> 5] = sw; r2[tid >> 5] = sm; }
    __syncthreads();
    if (tid == 0) {
        float tsw = 0.f, tsm = 0.f;
#pragma unroll
        for (int i = 0; i < 8; i++) { tsw += r1[i]; tsm += r2[i]; }
        if (isimg) {
            g_simg[b * CQ + c] = tsw;                    // colsum already includes 1/N
            g_mimg[b * CQ + c] = tsm * (1.0f / (float)NN);
        } else {
            g_spc[b * CK + (c - CQ)] = tsw;
        }
    }
}

// ---------------- head1: fused features ----------------
__global__ void __launch_bounds__(256) head1_kernel(const float *__restrict__ Wvi,
                                                    const float *__restrict__ bvi,
                                                    const float *__restrict__ Wvp,
                                                    const float *__restrict__ bvp,
                                                    const float *__restrict__ gamma) {
    const int blk = blockIdx.x, tid = threadIdx.x;
    const int co_l = tid >> 4, bb = tid & 15;
    if (blk < 16) {
        const int co = blk * 16 + co_l;
        const float *wrow = &Wvi[(size_t)co * CQ];
        const float *s = &g_simg[bb * CQ];
        float acc = 0.f;
        for (int ci = 0; ci < CQ; ci += 4) {
            float4 wv = *(const float4 *)&wrow[ci];
            float4 sv = *(const float4 *)&s[ci];
            acc += wv.x * sv.x + wv.y * sv.y + wv.z * sv.z + wv.w * sv.w;
        }
        const float g = gamma[0];
        g_fused[bb * FDIM + co] = g * (acc + bvi[co]) + g_mimg[bb * CQ + co];
    } else {
        const int co = (blk - 16) * 16 + co_l;
        const float *wrow = &Wvp[(size_t)co * CK];
        const float *s = &g_spc[bb * CK];
        float acc = 0.f;
        for (int ci = 0; ci < CK; ci += 4) {
            float4 wv = *(const float4 *)&wrow[ci];
            float4 sv = *(const float4 *)&s[ci];
            acc += wv.x * sv.x + wv.y * sv.y + wv.z * sv.z + wv.w * sv.w;
        }
        g_fused[bb * FDIM + CQ + co] = acc + bvp[co];
    }
}

// ---------------- head2: hidden layer ----------------
__global__ void __launch_bounds__(256) head2_kernel(const float *__restrict__ W1,
                                                    const float *__restrict__ b1) {
    const int blk = blockIdx.x, tid = threadIdx.x;
    const int co = blk * 16 + (tid >> 4), bb = tid & 15;
    const float *wrow = &W1[(size_t)co * FDIM];
    const float *f = &g_fused[bb * FDIM];
    float acc = 0.f;
    for (int ci = 0; ci < FDIM; ci += 4) {
        float4 wv = *(const float4 *)&wrow[ci];
        float4 fv = *(const float4 *)&f[ci];
        acc += wv.x * fv.x + wv.y * fv.y + wv.z * fv.z + wv.w * fv.w;
    }
    g_h[bb * HID + co] = fmaxf(acc + b1[co], 0.f);
}

// ---------------- head3: logits + log_softmax ----------------
__global__ void __launch_bounds__(256) head3_kernel(const float *__restrict__ W2,
                                                    const float *__restrict__ b2,
                                                    float *__restrict__ out) {
    const int b = blockIdx.x, tid = threadIdx.x;
    __shared__ float hs[HID];
    __shared__ float lg[NCLS];
    __shared__ float red[2];
    for (int i = tid; i < HID; i += 256) hs[i] = g_h[b * HID + i];
    __syncthreads();
    if (tid < NCLS) {
        const float *wrow = &W2[(size_t)tid * HID];
        float acc = 0.f;
        for (int ci = 0; ci < HID; ci += 4) {
            float4 wv = *(const float4 *)&wrow[ci];
            acc += wv.x * hs[ci] + wv.y * hs[ci + 1] + wv.z * hs[ci + 2] + wv.w * hs[ci + 3];
        }
        lg[tid] = acc + b2[tid];
    }
    __syncthreads();
    if (tid == 0) {
        float mx = -1e30f;
        for (int i = 0; i < NCLS; i++) mx = fmaxf(mx, lg[i]);
        float s = 0.f;
        for (int i = 0; i < NCLS; i++) s += expf(lg[i] - mx);
        red[0] = mx;
        red[1] = logf(s);
    }
    __syncthreads();
    if (tid < NCLS) out[b * NCLS + tid] = lg[tid] - red[0] - red[1];
}

// ---------------- launcher ----------------
extern "C" void kernel_launch(void *const *d_in, const int *in_sizes, int n_in,
                              void *d_out, int out_size) {
    const float *img   = (const float *)d_in[0];
    const float *pc2d  = (const float *)d_in[1];
    const float *Wq    = (const float *)d_in[2];
    const float *bq    = (const float *)d_in[3];
    const float *Wk    = (const float *)d_in[4];
    const float *bk    = (const float *)d_in[5];
    const float *Wvi   = (const float *)d_in[6];
    const float *bvi   = (const float *)d_in[7];
    const float *Wvp   = (const float *)d_in[8];
    const float *bvp   = (const float *)d_in[9];
    const float *gamma = (const float *)d_in[10];
    const float *W1    = (const float *)d_in[11];
    const float *b1    = (const float *)d_in[12];
    const float *W2    = (const float *)d_in[13];
    const float *b2    = (const float *)d_in[14];
    float *out = (float *)d_out;

    float *wqt, *wkt, *gq, *gk;
    cudaGetSymbolAddress((void **)&wqt, g_Wqt);
    cudaGetSymbolAddress((void **)&wkt, g_Wkt);
    cudaGetSymbolAddress((void **)&gq, g_Q);
    cudaGetSymbolAddress((void **)&gk, g_K);

    transpose_kernel<<<dim3(CQ / 32, CQ / 32), dim3(32, 8)>>>(Wq, wqt, CQ, CQ);
    transpose_kernel<<<dim3(CK / 32, CQ / 32), dim3(32, 8)>>>(Wk, wkt, CQ, CK);

    proj_kernel<<<dim3(NN / 128, CQ / 128, BB), 256>>>(wqt, img, bq, gq, CQ);
    proj_kernel<<<dim3(NN / 128, CQ / 128, BB), 256>>>(wkt, pc2d, bk, gk, CK);

    pass1_kernel<<<dim3(NN / 128, BB), 256>>>();
    pass2_kernel<<<dim3(NN / 128, BB), 256>>>();

    pool_kernel<<<dim3(FDIM, BB), 256>>>(img, pc2d);

    head1_kernel<<<16 + CK / 16, 256>>>(Wvi, bvi, Wvp, bvp, gamma);
    head2_kernel<<<HID / 16, 256>>>(W1, b1);
    head3_kernel<<<BB, 256>>>(W2, b2, out);
}

// round 10
// speedup vs baseline: 2.2604x; 2.2604x over previous
#include <cuda_runtime.h>
#include <cstdint>
#include <math.h>

// ---------------- problem dims ----------------
#define BB     16
#define CQ     256
#define CK     2048
#define NN     4096
#define NCLS   40
#define HID    1024
#define FDIM   2304

#define SASTRIDE 136   // floats per k-row in smem (128 + 8 pad): bank = (8k+m)%32

// ---------------- device scratch ----------------
__device__ float g_Wqt[CQ * CQ];                    // [ci][co]
__device__ float g_Wkt[CK * CQ];                    // [ci][co]
__device__ float g_Q[(size_t)BB * CQ * NN];         // [b][c][m]   (Q^T)
__device__ float g_K[(size_t)BB * CQ * NN];         // [b][c][n]   (K^T)
__device__ float g_S[(size_t)BB * NN * NN];         // [b][m][n]   1.07GB
__device__ float g_rmaxt[(size_t)BB * NN * 32];     // per-(row, ntile) max
__device__ float g_rsumt[(size_t)BB * NN * 32];     // per-(row, ntile) sumexp
__device__ float g_Z[BB * NN];
__device__ float g_colsum[BB * NN];
__device__ float g_simg[BB * CQ];
__device__ float g_mimg[BB * CQ];
__device__ float g_spc[BB * CK];
__device__ float g_fused[BB * FDIM];
__device__ float g_h[BB * HID];

// ---------------- helpers ----------------
__device__ __forceinline__ uint32_t tf32cvt(float f) {
    uint32_t r;
    asm("cvt.rna.tf32.f32 %0, %1;" : "=r"(r) : "f"(f));
    return r;
}

__device__ __forceinline__ void mma_tf32(float (&d)[4], const uint32_t (&a)[4],
                                         const uint32_t (&b)[2]) {
    asm volatile(
        "mma.sync.aligned.m16n8k8.row.col.f32.tf32.tf32.f32 "
        "{%0,%1,%2,%3}, {%4,%5,%6,%7}, {%8,%9}, {%0,%1,%2,%3};"
        : "+f"(d[0]), "+f"(d[1]), "+f"(d[2]), "+f"(d[3])
        : "r"(a[0]), "r"(a[1]), "r"(a[2]), "r"(a[3]), "r"(b[0]), "r"(b[1]));
}

// ---------------- weight transpose ----------------
__global__ void transpose_kernel(const float *__restrict__ in, float *__restrict__ out,
                                 int R, int C) {
    __shared__ float t[32][33];
    int c0 = blockIdx.x * 32, r0 = blockIdx.y * 32;
    int x = threadIdx.x, y = threadIdx.y;
#pragma unroll
    for (int i = y; i < 32; i += 8)
        t[i][x] = in[(size_t)(r0 + i) * C + c0 + x];
    __syncthreads();
#pragma unroll
    for (int i = y; i < 32; i += 8)
        out[(size_t)(c0 + i) * R + r0 + x] = t[x][i];
}

// ---------------- generic tf32 MMA GEMM ----------------
// Computes Out[m][n] = sum_k A[k][m] * B[k][n]   (both operands k-major)
// MODE 0: + bias[m] (proj, Out = projected^T [co][n])
// MODE 1: S epilogue: per-tile row max/sumexp stats -> g_rmaxt/g_rsumt
template <int MODE>
__global__ void __launch_bounds__(256, 2) gemm_mma(
    const float *__restrict__ A, const float *__restrict__ B,
    const float *__restrict__ bias, float *__restrict__ Out,
    int K, int ldA, int ldB, int ldo,
    size_t a_bs, size_t b_bs, size_t o_bs)
{
    __shared__ uint32_t sA[32 * SASTRIDE];
    __shared__ uint32_t sB[32 * SASTRIDE];
    __shared__ float2 sstat[128 * 4];

    const int tid = threadIdx.x;
    const int warp = tid >> 5, lane = tid & 31;
    const int qr = lane >> 2;          // 0..7
    const int qc = lane & 3;           // 0..3
    const int warpm = warp >> 2;       // 0..1
    const int warpn = warp & 3;        // 0..3
    const int bIdx = blockIdx.z;
    const int m0 = blockIdx.x * 128;
    const int n0 = blockIdx.y * 128;

    const float *Ag = A + (size_t)bIdx * a_bs + m0;
    const float *Bg = B + (size_t)bIdx * b_bs + n0;

    // tile-load lane mapping: k = i*8 + (warp>>2)*4 + (lane>>3), col4 = (warp&3)*32 + (lane&7)*4
    const int lk = ((warp >> 2) << 2) + (lane >> 3);
    const int lc = ((warp & 3) << 5) + ((lane & 7) << 2);

    float acc[4][4][4];
#pragma unroll
    for (int mf = 0; mf < 4; mf++)
#pragma unroll
        for (int nf = 0; nf < 4; nf++)
#pragma unroll
            for (int q = 0; q < 4; q++) acc[mf][nf][q] = 0.f;

    const int nkb = K >> 5;
    for (int kb = 0; kb < nkb; kb++) {
        const int kbase = kb << 5;
        __syncthreads();
#pragma unroll
        for (int i = 0; i < 4; i++) {
            const int k = i * 8 + lk;
            float4 va = *(const float4 *)&Ag[(size_t)(kbase + k) * ldA + lc];
            float4 vb = *(const float4 *)&Bg[(size_t)(kbase + k) * ldB + lc];
            uint4 ta = make_uint4(tf32cvt(va.x), tf32cvt(va.y), tf32cvt(va.z), tf32cvt(va.w));
            uint4 tb = make_uint4(tf32cvt(vb.x), tf32cvt(vb.y), tf32cvt(vb.z), tf32cvt(vb.w));
            *(uint4 *)&sA[k * SASTRIDE + lc] = ta;
            *(uint4 *)&sB[k * SASTRIDE + lc] = tb;
        }
        __syncthreads();

#pragma unroll
        for (int kk = 0; kk < 4; kk++) {
            const int kof = kk * 8 + qc;
            uint32_t afr[4][4];
#pragma unroll
            for (int mf = 0; mf < 4; mf++) {
                const int m = warpm * 64 + mf * 16 + qr;
                afr[mf][0] = sA[kof * SASTRIDE + m];
                afr[mf][1] = sA[kof * SASTRIDE + m + 8];
                afr[mf][2] = sA[(kof + 4) * SASTRIDE + m];
                afr[mf][3] = sA[(kof + 4) * SASTRIDE + m + 8];
            }
            uint32_t bfr[4][2];
#pragma unroll
            for (int nf = 0; nf < 4; nf++) {
                const int n = warpn * 32 + nf * 8 + qr;
                bfr[nf][0] = sB[kof * SASTRIDE + n];
                bfr[nf][1] = sB[(kof + 4) * SASTRIDE + n];
            }
#pragma unroll
            for (int mf = 0; mf < 4; mf++)
#pragma unroll
                for (int nf = 0; nf < 4; nf++)
                    mma_tf32(acc[mf][nf], afr[mf], bfr[nf]);
        }
    }

    // ---------------- epilogue ----------------
    const size_t ob = (size_t)bIdx * o_bs;

    if (MODE == 0) {
#pragma unroll
        for (int mf = 0; mf < 4; mf++) {
            const int r1 = m0 + warpm * 64 + mf * 16 + qr;
            const float bv1 = bias[r1], bv2 = bias[r1 + 8];
            const size_t ro1 = ob + (size_t)r1 * ldo + n0;
            const size_t ro2 = ob + (size_t)(r1 + 8) * ldo + n0;
#pragma unroll
            for (int nf = 0; nf < 4; nf++) {
                const int n = warpn * 32 + nf * 8 + qc * 2;
                *(float2 *)&Out[ro1 + n] =
                    make_float2(acc[mf][nf][0] + bv1, acc[mf][nf][1] + bv1);
                *(float2 *)&Out[ro2 + n] =
                    make_float2(acc[mf][nf][2] + bv2, acc[mf][nf][3] + bv2);
            }
        }
    } else {
#pragma unroll
        for (int mf = 0; mf < 4; mf++) {
            const int rl1 = warpm * 64 + mf * 16 + qr;
            const int rl2 = rl1 + 8;
            float mx1 = -3e38f, mx2 = -3e38f;
#pragma unroll
            for (int nf = 0; nf < 4; nf++) {
                mx1 = fmaxf(mx1, fmaxf(acc[mf][nf][0], acc[mf][nf][1]));
                mx2 = fmaxf(mx2, fmaxf(acc[mf][nf][2], acc[mf][nf][3]));
            }
            mx1 = fmaxf(mx1, __shfl_xor_sync(0xffffffffu, mx1, 1));
            mx1 = fmaxf(mx1, __shfl_xor_sync(0xffffffffu, mx1, 2));
            mx2 = fmaxf(mx2, __shfl_xor_sync(0xffffffffu, mx2, 1));
            mx2 = fmaxf(mx2, __shfl_xor_sync(0xffffffffu, mx2, 2));
            float s1 = 0.f, s2 = 0.f;
#pragma unroll
            for (int nf = 0; nf < 4; nf++) {
                s1 += __expf(acc[mf][nf][0] - mx1) + __expf(acc[mf][nf][1] - mx1);
                s2 += __expf(acc[mf][nf][2] - mx2) + __expf(acc[mf][nf][3] - mx2);
            }
            s1 += __shfl_xor_sync(0xffffffffu, s1, 1);
            s1 += __shfl_xor_sync(0xffffffffu, s1, 2);
            s2 += __shfl_xor_sync(0xffffffffu, s2, 1);
            s2 += __shfl_xor_sync(0xffffffffu, s2, 2);
            if (qc == 0) {
                sstat[rl1 * 4 + warpn] = make_float2(mx1, s1);
                sstat[rl2 * 4 + warpn] = make_float2(mx2, s2);
            }
            const size_t ro1 = ob + (size_t)(m0 + rl1) * ldo + n0;
            const size_t ro2 = ob + (size_t)(m0 + rl2) * ldo + n0;
#pragma unroll
            for (int nf = 0; nf < 4; nf++) {
                const int n = warpn * 32 + nf * 8 + qc * 2;
                *(float2 *)&Out[ro1 + n] = make_float2(acc[mf][nf][0], acc[mf][nf][1]);
                *(float2 *)&Out[ro2 + n] = make_float2(acc[mf][nf][2], acc[mf][nf][3]);
            }
        }
        __syncthreads();
        if (tid < 128) {
            float2 a0 = sstat[tid * 4 + 0], a1 = sstat[tid * 4 + 1];
            float2 a2 = sstat[tid * 4 + 2], a3 = sstat[tid * 4 + 3];
            float M = fmaxf(fmaxf(a0.x, a1.x), fmaxf(a2.x, a3.x));
            float S = a0.y * __expf(a0.x - M) + a1.y * __expf(a1.x - M) +
                      a2.y * __expf(a2.x - M) + a3.y * __expf(a3.x - M);
            size_t idx = (((size_t)bIdx * NN + m0 + tid) << 5) + blockIdx.y;
            g_rmaxt[idx] = M;
            g_rsumt[idx] = S;
        }
    }
}

// ---------------- Z combine: Z[m] = logsumexp over 32 tile stats ----------------
__global__ void __launch_bounds__(256) zcombine_kernel() {
    const size_t row = (size_t)blockIdx.x * 256 + threadIdx.x;
    const size_t base = row << 5;
    float M = -3e38f;
#pragma unroll 8
    for (int i = 0; i < 32; i++) M = fmaxf(M, g_rmaxt[base + i]);
    float S = 0.f;
#pragma unroll 8
    for (int i = 0; i < 32; i++) S += g_rsumt[base + i] * __expf(g_rmaxt[base + i] - M);
    g_Z[row] = M + logf(S);
}

// ---------------- colsum[n] = (1/N) * sum_m exp(S[m,n] - Z[m]) ----------------
__global__ void __launch_bounds__(256) colsum_kernel() {
    __shared__ float zs[NN];
    const int b = blockIdx.y;
    const int n = blockIdx.x * 256 + threadIdx.x;
    for (int i = threadIdx.x; i < NN; i += 256) zs[i] = g_Z[b * NN + i];
    __syncthreads();
    float acc = 0.f;
    const float *Sc = &g_S[(size_t)b * NN * NN + n];
#pragma unroll 1
    for (int m = 0; m < NN; m += 8) {
        float v[8];
#pragma unroll
        for (int i = 0; i < 8; i++) v[i] = Sc[(size_t)(m + i) * NN];
#pragma unroll
        for (int i = 0; i < 8; i++) acc += __expf(v[i] - zs[m + i]);
    }
    g_colsum[b * NN + n] = acc * (1.0f / (float)NN);
}

// ---------------- weighted pooling ----------------
__global__ void __launch_bounds__(256) pool_kernel(const float *__restrict__ img,
                                                   const float *__restrict__ pc) {
    const int b = blockIdx.y, c = blockIdx.x, tid = threadIdx.x;
    const bool isimg = (c < CQ);
    const float *X = isimg ? img + ((size_t)(b * CQ + c)) * NN
                           : pc + ((size_t)(b * CK + (c - CQ))) * NN;
    const float *w = &g_colsum[b * NN];
    float sw = 0.f, sm = 0.f;
#pragma unroll
    for (int j = 0; j < 4; j++) {
        float4 xv = *(const float4 *)&X[tid * 4 + j * 1024];
        float4 wv = *(const float4 *)&w[tid * 4 + j * 1024];
        sw += xv.x * wv.x + xv.y * wv.y + xv.z * wv.z + xv.w * wv.w;
        sm += (xv.x + xv.y) + (xv.z + xv.w);
    }
#pragma unroll
    for (int off = 16; off; off >>= 1) {
        sw += __shfl_xor_sync(0xffffffffu, sw, off);
        sm += __shfl_xor_sync(0xffffffffu, sm, off);
    }
    __shared__ float r1[8], r2[8];
    if ((tid & 31) == 0) { r1[tid >> 5] = sw; r2[tid >> 5] = sm; }
    __syncthreads();
    if (tid == 0) {
        float tsw = 0.f, tsm = 0.f;
#pragma unroll
        for (int i = 0; i < 8; i++) { tsw += r1[i]; tsm += r2[i]; }
        if (isimg) {
            g_simg[b * CQ + c] = tsw;
            g_mimg[b * CQ + c] = tsm * (1.0f / (float)NN);
        } else {
            g_spc[b * CK + (c - CQ)] = tsw;
        }
    }
}

// ---------------- heads ----------------
__global__ void __launch_bounds__(256) head1_kernel(const float *__restrict__ Wvi,
                                                    const float *__restrict__ bvi,
                                                    const float *__restrict__ Wvp,
                                                    const float *__restrict__ bvp,
                                                    const float *__restrict__ gamma) {
    const int blk = blockIdx.x, tid = threadIdx.x;
    const int co_l = tid >> 4, bb = tid & 15;
    if (blk < 16) {
        const int co = blk * 16 + co_l;
        const float *wrow = &Wvi[(size_t)co * CQ];
        const float *s = &g_simg[bb * CQ];
        float acc = 0.f;
        for (int ci = 0; ci < CQ; ci += 4) {
            float4 wv = *(const float4 *)&wrow[ci];
            float4 sv = *(const float4 *)&s[ci];
            acc += wv.x * sv.x + wv.y * sv.y + wv.z * sv.z + wv.w * sv.w;
        }
        const float g = gamma[0];
        g_fused[bb * FDIM + co] = g * (acc + bvi[co]) + g_mimg[bb * CQ + co];
    } else {
        const int co = (blk - 16) * 16 + co_l;
        const float *wrow = &Wvp[(size_t)co * CK];
        const float *s = &g_spc[bb * CK];
        float acc = 0.f;
        for (int ci = 0; ci < CK; ci += 4) {
            float4 wv = *(const float4 *)&wrow[ci];
            float4 sv = *(const float4 *)&s[ci];
            acc += wv.x * sv.x + wv.y * sv.y + wv.z * sv.z + wv.w * sv.w;
        }
        g_fused[bb * FDIM + CQ + co] = acc + bvp[co];
    }
}

__global__ void __launch_bounds__(256) head2_kernel(const float *__restrict__ W1,
                                                    const float *__restrict__ b1) {
    const int blk = blockIdx.x, tid = threadIdx.x;
    const int co = blk * 16 + (tid >> 4), bb = tid & 15;
    const float *wrow = &W1[(size_t)co * FDIM];
    const float *f = &g_fused[bb * FDIM];
    float acc = 0.f;
    for (int ci = 0; ci < FDIM; ci += 4) {
        float4 wv = *(const float4 *)&wrow[ci];
        float4 fv = *(const float4 *)&f[ci];
        acc += wv.x * fv.x + wv.y * fv.y + wv.z * fv.z + wv.w * fv.w;
    }
    g_h[bb * HID + co] = fmaxf(acc + b1[co], 0.f);
}

__global__ void __launch_bounds__(256) head3_kernel(const float *__restrict__ W2,
                                                    const float *__restrict__ b2,
                                                    float *__restrict__ out) {
    const int b = blockIdx.x, tid = threadIdx.x;
    __shared__ float hs[HID];
    __shared__ float lg[NCLS];
    __shared__ float red[2];
    for (int i = tid; i < HID; i += 256) hs[i] = g_h[b * HID + i];
    __syncthreads();
    if (tid < NCLS) {
        const float *wrow = &W2[(size_t)tid * HID];
        float acc = 0.f;
        for (int ci = 0; ci < HID; ci += 4) {
            float4 wv = *(const float4 *)&wrow[ci];
            acc += wv.x * hs[ci] + wv.y * hs[ci + 1] + wv.z * hs[ci + 2] + wv.w * hs[ci + 3];
        }
        lg[tid] = acc + b2[tid];
    }
    __syncthreads();
    if (tid == 0) {
        float mx = -1e30f;
        for (int i = 0; i < NCLS; i++) mx = fmaxf(mx, lg[i]);
        float s = 0.f;
        for (int i = 0; i < NCLS; i++) s += expf(lg[i] - mx);
        red[0] = mx;
        red[1] = logf(s);
    }
    __syncthreads();
    if (tid < NCLS) out[b * NCLS + tid] = lg[tid] - red[0] - red[1];
}

// ---------------- launcher ----------------
extern "C" void kernel_launch(void *const *d_in, const int *in_sizes, int n_in,
                              void *d_out, int out_size) {
    const float *img   = (const float *)d_in[0];
    const float *pc2d  = (const float *)d_in[1];
    const float *Wq    = (const float *)d_in[2];
    const float *bq    = (const float *)d_in[3];
    const float *Wk    = (const float *)d_in[4];
    const float *bk    = (const float *)d_in[5];
    const float *Wvi   = (const float *)d_in[6];
    const float *bvi   = (const float *)d_in[7];
    const float *Wvp   = (const float *)d_in[8];
    const float *bvp   = (const float *)d_in[9];
    const float *gamma = (const float *)d_in[10];
    const float *W1    = (const float *)d_in[11];
    const float *b1    = (const float *)d_in[12];
    const float *W2    = (const float *)d_in[13];
    const float *b2    = (const float *)d_in[14];
    float *out = (float *)d_out;

    float *wqt, *wkt, *gq, *gk, *gs;
    cudaGetSymbolAddress((void **)&wqt, g_Wqt);
    cudaGetSymbolAddress((void **)&wkt, g_Wkt);
    cudaGetSymbolAddress((void **)&gq, g_Q);
    cudaGetSymbolAddress((void **)&gk, g_K);
    cudaGetSymbolAddress((void **)&gs, g_S);

    // weight transposes: Wq [co][ci] -> Wqt [ci][co]
    transpose_kernel<<<dim3(CQ / 32, CQ / 32), dim3(32, 8)>>>(Wq, wqt, CQ, CQ);
    transpose_kernel<<<dim3(CK / 32, CQ / 32), dim3(32, 8)>>>(Wk, wkt, CQ, CK);

    // Q^T[co][n] = sum_ci Wqt[ci][co] * img[ci][n] + bq[co]
    gemm_mma<0><<<dim3(CQ / 128, NN / 128, BB), 256>>>(
        wqt, img, bq, gq, CQ, CQ, NN, NN,
        (size_t)0, (size_t)NN * CQ, (size_t)CQ * NN);

    // K^T[co][n] = sum_ci Wkt[ci][co] * pc2d[ci][n] + bk[co]
    gemm_mma<0><<<dim3(CQ / 128, NN / 128, BB), 256>>>(
        wkt, pc2d, bk, gk, CK, CQ, NN, NN,
        (size_t)0, (size_t)NN * CK, (size_t)CQ * NN);

    // S[m][n] = sum_c Q^T[c][m] * K^T[c][n]  (+ per-tile row stats)
    gemm_mma<1><<<dim3(NN / 128, NN / 128, BB), 256>>>(
        gq, gk, nullptr, gs, CQ, NN, NN, NN,
        (size_t)CQ * NN, (size_t)CQ * NN, (size_t)NN * NN);

    zcombine_kernel<<<(BB * NN) / 256, 256>>>();
    colsum_kernel<<<dim3(NN / 256, BB), 256>>>();

    pool_kernel<<<dim3(FDIM, BB), 256>>>(img, pc2d);

    head1_kernel<<<16 + CK / 16, 256>>>(Wvi, bvi, Wvp, bvp, gamma);
    head2_kernel<<<HID / 16, 256>>>(W1, b1);
    head3_kernel<<<BB, 256>>>(W2, b2, out);
}

// round 13
// speedup vs baseline: 2.2946x; 1.0151x over previous
#include <cuda_runtime.h>
#include <cstdint>
#include <math.h>

// ---------------- problem dims ----------------
#define BB     16
#define CQ     256
#define CK     2048
#define NN     4096
#define NCLS   40
#define HID    1024
#define FDIM   2304

#define SASTRIDE 136   // floats per k-row in smem (128 + 8 pad): bank = (8k+m)%32
#define STAGE_BYTES 34816          // (32*SASTRIDE*4) * 2 tiles = 17408*2
#define TILE_BYTES  17408

// ---------------- device scratch ----------------
__device__ float g_Wqt[CQ * CQ];                    // [ci][co]
__device__ float g_Wkt[CK * CQ];                    // [ci][co]
__device__ float g_Q[(size_t)BB * CQ * NN];         // [b][c][m]   (Q^T)
__device__ float g_K[(size_t)BB * CQ * NN];         // [b][c][n]   (K^T)
__device__ float g_rmaxt[(size_t)BB * NN * 32];     // per-(row, ntile) max
__device__ float g_rsumt[(size_t)BB * NN * 32];     // per-(row, ntile) sumexp
__device__ float g_Z[BB * NN];
__device__ float g_colsum[BB * NN];
__device__ float g_simg[BB * CQ];
__device__ float g_mimg[BB * CQ];
__device__ float g_spc[BB * CK];
__device__ float g_fused[BB * FDIM];
__device__ float g_h[BB * HID];

// ---------------- helpers ----------------
__device__ __forceinline__ uint32_t smem_u32(const void *p) {
    uint32_t a;
    asm("{ .reg .u64 t; cvta.to.shared.u64 t, %1; cvt.u32.u64 %0, t; }" : "=r"(a) : "l"(p));
    return a;
}

__device__ __forceinline__ void cp16(uint32_t dst, const void *src) {
    asm volatile("cp.async.cg.shared.global [%0], [%1], 16;" :: "r"(dst), "l"(src) : "memory");
}

__device__ __forceinline__ void mma_tf32(float (&d)[4], const uint32_t (&a)[4],
                                         const uint32_t (&b)[2]) {
    asm volatile(
        "mma.sync.aligned.m16n8k8.row.col.f32.tf32.tf32.f32 "
        "{%0,%1,%2,%3}, {%4,%5,%6,%7}, {%8,%9}, {%0,%1,%2,%3};"
        : "+f"(d[0]), "+f"(d[1]), "+f"(d[2]), "+f"(d[3])
        : "r"(a[0]), "r"(a[1]), "r"(a[2]), "r"(a[3]), "r"(b[0]), "r"(b[1]));
}

// ---------------- init: zero colsum (atomically accumulated each launch) ----------------
__global__ void init_kernel() {
    int i = blockIdx.x * 256 + threadIdx.x;
    if (i < BB * NN) g_colsum[i] = 0.f;
}

// ---------------- weight transpose ----------------
__global__ void transpose_kernel(const float *__restrict__ in, float *__restrict__ out,
                                 int R, int C) {
    __shared__ float t[32][33];
    int c0 = blockIdx.x * 32, r0 = blockIdx.y * 32;
    int x = threadIdx.x, y = threadIdx.y;
#pragma unroll
    for (int i = y; i < 32; i += 8)
        t[i][x] = in[(size_t)(r0 + i) * C + c0 + x];
    __syncthreads();
#pragma unroll
    for (int i = y; i < 32; i += 8)
        out[(size_t)(c0 + i) * R + r0 + x] = t[x][i];
}

// ---------------- generic tf32 MMA GEMM, cp.async double-buffered ----------------
// Out[m][n] = sum_k A[k][m] * B[k][n]   (both operands k-major)
// MODE 0: proj (+bias[m], store Out)
// MODE 1: S pass1: per-tile row max/sumexp stats only (no store)
// MODE 2: S pass2: recompute, exp(S - Z), column sums -> atomicAdd g_colsum
template <int MODE>
__global__ void __launch_bounds__(256) gemm_mma(
    const float *__restrict__ A, const float *__restrict__ B,
    const float *__restrict__ bias, float *__restrict__ Out,
    int K, int ldA, int ldB, int ldo,
    size_t a_bs, size_t b_bs, size_t o_bs)
{
    extern __shared__ char dsm[];
    __shared__ float2 sstat[128 * 4];
    __shared__ float zrow[128];
    __shared__ float colacc[128];

    const int tid = threadIdx.x;
    const int warp = tid >> 5, lane = tid & 31;
    const int qr = lane >> 2;          // 0..7
    const int qc = lane & 3;           // 0..3
    const int warpm = warp >> 2;       // 0..1
    const int warpn = warp & 3;        // 0..3
    const int bIdx = blockIdx.z;
    const int m0 = blockIdx.x * 128;
    const int n0 = blockIdx.y * 128;

    const float *Ag = A + (size_t)bIdx * a_bs + m0;
    const float *Bg = B + (size_t)bIdx * b_bs + n0;

    const uint32_t smem_base = smem_u32(dsm);

    // tile-load lane mapping: k = i*8 + lk, col4 = lc (4 floats)
    const int lk = ((warp >> 2) << 2) + (lane >> 3);
    const int lc = ((warp & 3) << 5) + ((lane & 7) << 2);

    if (MODE == 2) {
        if (tid < 128) {
            zrow[tid] = g_Z[bIdx * NN + m0 + tid];
            colacc[tid] = 0.f;
        }
    }

    float acc[4][4][4];
#pragma unroll
    for (int mf = 0; mf < 4; mf++)
#pragma unroll
        for (int nf = 0; nf < 4; nf++)
#pragma unroll
            for (int q = 0; q < 4; q++) acc[mf][nf][q] = 0.f;

#define LOAD_STAGE(kb, st) do {                                                    \
        const float *Ab = Ag + (size_t)((kb) << 5) * ldA;                          \
        const float *Bb = Bg + (size_t)((kb) << 5) * ldB;                          \
        const uint32_t da = smem_base + (st) * STAGE_BYTES;                        \
        const uint32_t db = da + TILE_BYTES;                                       \
        _Pragma("unroll")                                                          \
        for (int i = 0; i < 4; i++) {                                              \
            const int k = i * 8 + lk;                                              \
            cp16(da + (k * SASTRIDE + lc) * 4, Ab + (size_t)k * ldA + lc);         \
            cp16(db + (k * SASTRIDE + lc) * 4, Bb + (size_t)k * ldB + lc);         \
        }                                                                          \
        asm volatile("cp.async.commit_group;" ::: "memory");                       \
    } while (0)

    const int nkb = K >> 5;
    LOAD_STAGE(0, 0);

    for (int kb = 0; kb < nkb; kb++) {
        if (kb + 1 < nkb) {
            LOAD_STAGE(kb + 1, (kb + 1) & 1);
            asm volatile("cp.async.wait_group 1;" ::: "memory");
        } else {
            asm volatile("cp.async.wait_group 0;" ::: "memory");
        }
        __syncthreads();

        const int st = kb & 1;
        const uint32_t *sA = (const uint32_t *)(dsm + st * STAGE_BYTES);
        const uint32_t *sB = (const uint32_t *)(dsm + st * STAGE_BYTES + TILE_BYTES);

#pragma unroll
        for (int kk = 0; kk < 4; kk++) {
            const int kof = kk * 8 + qc;
            uint32_t afr[4][4];
#pragma unroll
            for (int mf = 0; mf < 4; mf++) {
                const int m = warpm * 64 + mf * 16 + qr;
                afr[mf][0] = sA[kof * SASTRIDE + m];
                afr[mf][1] = sA[kof * SASTRIDE + m + 8];
                afr[mf][2] = sA[(kof + 4) * SASTRIDE + m];
                afr[mf][3] = sA[(kof + 4) * SASTRIDE + m + 8];
            }
            uint32_t bfr[4][2];
#pragma unroll
            for (int nf = 0; nf < 4; nf++) {
                const int n = warpn * 32 + nf * 8 + qr;
                bfr[nf][0] = sB[kof * SASTRIDE + n];
                bfr[nf][1] = sB[(kof + 4) * SASTRIDE + n];
            }
#pragma unroll
            for (int mf = 0; mf < 4; mf++)
#pragma unroll
                for (int nf = 0; nf < 4; nf++)
                    mma_tf32(acc[mf][nf], afr[mf], bfr[nf]);
        }
        __syncthreads();
    }
#undef LOAD_STAGE

    // ---------------- epilogue ----------------
    if (MODE == 0) {
        const size_t ob = (size_t)bIdx * o_bs;
#pragma unroll
        for (int mf = 0; mf < 4; mf++) {
            const int r1 = m0 + warpm * 64 + mf * 16 + qr;
            const float bv1 = bias[r1], bv2 = bias[r1 + 8];
            const size_t ro1 = ob + (size_t)r1 * ldo + n0;
            const size_t ro2 = ob + (size_t)(r1 + 8) * ldo + n0;
#pragma unroll
            for (int nf = 0; nf < 4; nf++) {
                const int n = warpn * 32 + nf * 8 + qc * 2;
                *(float2 *)&Out[ro1 + n] =
                    make_float2(acc[mf][nf][0] + bv1, acc[mf][nf][1] + bv1);
                *(float2 *)&Out[ro2 + n] =
                    make_float2(acc[mf][nf][2] + bv2, acc[mf][nf][3] + bv2);
            }
        }
    } else if (MODE == 1) {
#pragma unroll
        for (int mf = 0; mf < 4; mf++) {
            const int rl1 = warpm * 64 + mf * 16 + qr;
            const int rl2 = rl1 + 8;
            float mx1 = -3e38f, mx2 = -3e38f;
#pragma unroll
            for (int nf = 0; nf < 4; nf++) {
                mx1 = fmaxf(mx1, fmaxf(acc[mf][nf][0], acc[mf][nf][1]));
                mx2 = fmaxf(mx2, fmaxf(acc[mf][nf][2], acc[mf][nf][3]));
            }
            mx1 = fmaxf(mx1, __shfl_xor_sync(0xffffffffu, mx1, 1));
            mx1 = fmaxf(mx1, __shfl_xor_sync(0xffffffffu, mx1, 2));
            mx2 = fmaxf(mx2, __shfl_xor_sync(0xffffffffu, mx2, 1));
            mx2 = fmaxf(mx2, __shfl_xor_sync(0xffffffffu, mx2, 2));
            float s1 = 0.f, s2 = 0.f;
#pragma unroll
            for (int nf = 0; nf < 4; nf++) {
                s1 += __expf(acc[mf][nf][0] - mx1) + __expf(acc[mf][nf][1] - mx1);
                s2 += __expf(acc[mf][nf][2] - mx2) + __expf(acc[mf][nf][3] - mx2);
            }
            s1 += __shfl_xor_sync(0xffffffffu, s1, 1);
            s1 += __shfl_xor_sync(0xffffffffu, s1, 2);
            s2 += __shfl_xor_sync(0xffffffffu, s2, 1);
            s2 += __shfl_xor_sync(0xffffffffu, s2, 2);
            if (qc == 0) {
                sstat[rl1 * 4 + warpn] = make_float2(mx1, s1);
                sstat[rl2 * 4 + warpn] = make_float2(mx2, s2);
            }
        }
        __syncthreads();
        if (tid < 128) {
            float2 a0 = sstat[tid * 4 + 0], a1 = sstat[tid * 4 + 1];
            float2 a2 = sstat[tid * 4 + 2], a3 = sstat[tid * 4 + 3];
            float M = fmaxf(fmaxf(a0.x, a1.x), fmaxf(a2.x, a3.x));
            float S = a0.y * __expf(a0.x - M) + a1.y * __expf(a1.x - M) +
                      a2.y * __expf(a2.x - M) + a3.y * __expf(a3.x - M);
            size_t idx = (((size_t)bIdx * NN + m0 + tid) << 5) + blockIdx.y;
            g_rmaxt[idx] = M;
            g_rsumt[idx] = S;
        }
    } else {
        // MODE 2: column sums of exp(S - Z[m])
        float csum[4][2];
#pragma unroll
        for (int nf = 0; nf < 4; nf++) { csum[nf][0] = 0.f; csum[nf][1] = 0.f; }
#pragma unroll
        for (int mf = 0; mf < 4; mf++) {
            const int rl1 = warpm * 64 + mf * 16 + qr;
            const float z1 = zrow[rl1], z2 = zrow[rl1 + 8];
#pragma unroll
            for (int nf = 0; nf < 4; nf++) {
                csum[nf][0] += __expf(acc[mf][nf][0] - z1) + __expf(acc[mf][nf][2] - z2);
                csum[nf][1] += __expf(acc[mf][nf][1] - z1) + __expf(acc[mf][nf][3] - z2);
            }
        }
        // reduce over qr (lanes stride 4): lanes with qr==0 hold warp totals
#pragma unroll
        for (int nf = 0; nf < 4; nf++) {
#pragma unroll
            for (int off = 4; off < 32; off <<= 1) {
                csum[nf][0] += __shfl_xor_sync(0xffffffffu, csum[nf][0], off);
                csum[nf][1] += __shfl_xor_sync(0xffffffffu, csum[nf][1], off);
            }
        }
        if (qr == 0) {
#pragma unroll
            for (int nf = 0; nf < 4; nf++) {
                const int n = warpn * 32 + nf * 8 + qc * 2;
                atomicAdd(&colacc[n], csum[nf][0]);
                atomicAdd(&colacc[n + 1], csum[nf][1]);
            }
        }
        __syncthreads();
        if (tid < 128)
            atomicAdd(&g_colsum[bIdx * NN + n0 + tid], colacc[tid] * (1.0f / (float)NN));
    }
}

// ---------------- Z combine: Z[m] = logsumexp over 32 tile stats ----------------
__global__ void __launch_bounds__(256) zcombine_kernel() {
    const size_t row = (size_t)blockIdx.x * 256 + threadIdx.x;
    const size_t base = row << 5;
    float M = -3e38f;
#pragma unroll 8
    for (int i = 0; i < 32; i++) M = fmaxf(M, g_rmaxt[base + i]);
    float S = 0.f;
#pragma unroll 8
    for (int i = 0; i < 32; i++) S += g_rsumt[base + i] * __expf(g_rmaxt[base + i] - M);
    g_Z[row] = M + logf(S);
}

// ---------------- weighted pooling ----------------
__global__ void __launch_bounds__(256) pool_kernel(const float *__restrict__ img,
                                                   const float *__restrict__ pc) {
    const int b = blockIdx.y, c = blockIdx.x, tid = threadIdx.x;
    const bool isimg = (c < CQ);
    const float *X = isimg ? img + ((size_t)(b * CQ + c)) * NN
                           : pc + ((size_t)(b * CK + (c - CQ))) * NN;
    const float *w = &g_colsum[b * NN];
    float sw = 0.f, sm = 0.f;
#pragma unroll
    for (int j = 0; j < 4; j++) {
        float4 xv = *(const float4 *)&X[tid * 4 + j * 1024];
        float4 wv = *(const float4 *)&w[tid * 4 + j * 1024];
        sw += xv.x * wv.x + xv.y * wv.y + xv.z * wv.z + xv.w * wv.w;
        sm += (xv.x + xv.y) + (xv.z + xv.w);
    }
#pragma unroll
    for (int off = 16; off; off >>= 1) {
        sw += __shfl_xor_sync(0xffffffffu, sw, off);
        sm += __shfl_xor_sync(0xffffffffu, sm, off);
    }
    __shared__ float r1[8], r2[8];
    if ((tid & 31) == 0) { r1[tid >> 5] = sw; r2[tid >> 5] = sm; }
    __syncthreads();
    if (tid == 0) {
        float tsw = 0.f, tsm = 0.f;
#pragma unroll
        for (int i = 0; i < 8; i++) { tsw += r1[i]; tsm += r2[i]; }
        if (isimg) {
            g_simg[b * CQ + c] = tsw;
            g_mimg[b * CQ + c] = tsm * (1.0f / (float)NN);
        } else {
            g_spc[b * CK + (c - CQ)] = tsw;
        }
    }
}

// ---------------- heads ----------------
__global__ void __launch_bounds__(256) head1_kernel(const float *__restrict__ Wvi,
                                                    const float *__restrict__ bvi,
                                                    const float *__restrict__ Wvp,
                                                    const float *__restrict__ bvp,
                                                    const float *__restrict__ gamma) {
    const int blk = blockIdx.x, tid = threadIdx.x;
    const int co_l = tid >> 4, bb = tid & 15;
    if (blk < 16) {
        const int co = blk * 16 + co_l;
        const float *wrow = &Wvi[(size_t)co * CQ];
        const float *s = &g_simg[bb * CQ];
        float acc = 0.f;
        for (int ci = 0; ci < CQ; ci += 4) {
            float4 wv = *(const float4 *)&wrow[ci];
            float4 sv = *(const float4 *)&s[ci];
            acc += wv.x * sv.x + wv.y * sv.y + wv.z * sv.z + wv.w * sv.w;
        }
        const float g = gamma[0];
        g_fused[bb * FDIM + co] = g * (acc + bvi[co]) + g_mimg[bb * CQ + co];
    } else {
        const int co = (blk - 16) * 16 + co_l;
        const float *wrow = &Wvp[(size_t)co * CK];
        const float *s = &g_spc[bb * CK];
        float acc = 0.f;
        for (int ci = 0; ci < CK; ci += 4) {
            float4 wv = *(const float4 *)&wrow[ci];
            float4 sv = *(const float4 *)&s[ci];
            acc += wv.x * sv.x + wv.y * sv.y + wv.z * sv.z + wv.w * sv.w;
        }
        g_fused[bb * FDIM + CQ + co] = acc + bvp[co];
    }
}

__global__ void __launch_bounds__(256) head2_kernel(const float *__restrict__ W1,
                                                    const float *__restrict__ b1) {
    const int blk = blockIdx.x, tid = threadIdx.x;
    const int co = blk * 16 + (tid >> 4), bb = tid & 15;
    const float *wrow = &W1[(size_t)co * FDIM];
    const float *f = &g_fused[bb * FDIM];
    float acc = 0.f;
    for (int ci = 0; ci < FDIM; ci += 4) {
        float4 wv = *(const float4 *)&wrow[ci];
        float4 fv = *(const float4 *)&f[ci];
        acc += wv.x * fv.x + wv.y * fv.y + wv.z * fv.z + wv.w * fv.w;
    }
    g_h[bb * HID + co] = fmaxf(acc + b1[co], 0.f);
}

__global__ void __launch_bounds__(256) head3_kernel(const float *__restrict__ W2,
                                                    const float *__restrict__ b2,
                                                    float *__restrict__ out) {
    const int b = blockIdx.x, tid = threadIdx.x;
    __shared__ float hs[HID];
    __shared__ float lg[NCLS];
    __shared__ float red[2];
    for (int i = tid; i < HID; i += 256) hs[i] = g_h[b * HID + i];
    __syncthreads();
    if (tid < NCLS) {
        const float *wrow = &W2[(size_t)tid * HID];
        float acc = 0.f;
        for (int ci = 0; ci < HID; ci += 4) {
            float4 wv = *(const float4 *)&wrow[ci];
            acc += wv.x * hs[ci] + wv.y * hs[ci + 1] + wv.z * hs[ci + 2] + wv.w * hs[ci + 3];
        }
        lg[tid] = acc + b2[tid];
    }
    __syncthreads();
    if (tid == 0) {
        float mx = -1e30f;
        for (int i = 0; i < NCLS; i++) mx = fmaxf(mx, lg[i]);
        float s = 0.f;
        for (int i = 0; i < NCLS; i++) s += expf(lg[i] - mx);
        red[0] = mx;
        red[1] = logf(s);
    }
    __syncthreads();
    if (tid < NCLS) out[b * NCLS + tid] = lg[tid] - red[0] - red[1];
}

// ---------------- launcher ----------------
extern "C" void kernel_launch(void *const *d_in, const int *in_sizes, int n_in,
                              void *d_out, int out_size) {
    const float *img   = (const float *)d_in[0];
    const float *pc2d  = (const float *)d_in[1];
    const float *Wq    = (const float *)d_in[2];
    const float *bq    = (const float *)d_in[3];
    const float *Wk    = (const float *)d_in[4];
    const float *bk    = (const float *)d_in[5];
    const float *Wvi   = (const float *)d_in[6];
    const float *bvi   = (const float *)d_in[7];
    const float *Wvp   = (const float *)d_in[8];
    const float *bvp   = (const float *)d_in[9];
    const float *gamma = (const float *)d_in[10];
    const float *W1    = (const float *)d_in[11];
    const float *b1    = (const float *)d_in[12];
    const float *W2    = (const float *)d_in[13];
    const float *b2    = (const float *)d_in[14];
    float *out = (float *)d_out;

    float *wqt, *wkt, *gq, *gk;
    cudaGetSymbolAddress((void **)&wqt, g_Wqt);
    cudaGetSymbolAddress((void **)&wkt, g_Wkt);
    cudaGetSymbolAddress((void **)&gq, g_Q);
    cudaGetSymbolAddress((void **)&gk, g_K);

    const int DSMEM = 2 * STAGE_BYTES;   // 69632
    cudaFuncSetAttribute(gemm_mma<0>, cudaFuncAttributeMaxDynamicSharedMemorySize, DSMEM);
    cudaFuncSetAttribute(gemm_mma<1>, cudaFuncAttributeMaxDynamicSharedMemorySize, DSMEM);
    cudaFuncSetAttribute(gemm_mma<2>, cudaFuncAttributeMaxDynamicSharedMemorySize, DSMEM);

    init_kernel<<<(BB * NN + 255) / 256, 256>>>();

    // weight transposes: Wq [co][ci] -> Wqt [ci][co]
    transpose_kernel<<<dim3(CQ / 32, CQ / 32), dim3(32, 8)>>>(Wq, wqt, CQ, CQ);
    transpose_kernel<<<dim3(CK / 32, CQ / 32), dim3(32, 8)>>>(Wk, wkt, CQ, CK);

    // Q^T[co][n] = sum_ci Wqt[ci][co] * img[ci][n] + bq[co]
    gemm_mma<0><<<dim3(CQ / 128, NN / 128, BB), 256, DSMEM>>>(
        wqt, img, bq, gq, CQ, CQ, NN, NN,
        (size_t)0, (size_t)NN * CQ, (size_t)CQ * NN);

    // K^T[co][n] = sum_ci Wkt[ci][co] * pc2d[ci][n] + bk[co]
    gemm_mma<0><<<dim3(CQ / 128, NN / 128, BB), 256, DSMEM>>>(
        wkt, pc2d, bk, gk, CK, CQ, NN, NN,
        (size_t)0, (size_t)NN * CK, (size_t)CQ * NN);

    // S pass1: stats only
    gemm_mma<1><<<dim3(NN / 128, NN / 128, BB), 256, DSMEM>>>(
        gq, gk, nullptr, nullptr, CQ, NN, NN, 0,
        (size_t)CQ * NN, (size_t)CQ * NN, 0);

    zcombine_kernel<<<(BB * NN) / 256, 256>>>();

    // S pass2: recompute, accumulate column sums of exp(S - Z)
    gemm_mma<2><<<dim3(NN / 128, NN / 128, BB), 256, DSMEM>>>(
        gq, gk, nullptr, nullptr, CQ, NN, NN, 0,
        (size_t)CQ * NN, (size_t)CQ * NN, 0);

    pool_kernel<<<dim3(FDIM, BB), 256>>>(img, pc2d);

    head1_kernel<<<16 + CK / 16, 256>>>(Wvi, bvi, Wvp, bvp, gamma);
    head2_kernel<<<HID / 16, 256>>>(W1, b1);
    head3_kernel<<<BB, 256>>>(W2, b2, out);
}